// round 14
// baseline (speedup 1.0000x reference)
#include <cuda_runtime.h>
#include <cuda_fp16.h>
#include <math.h>
#include <stdint.h>

// Problem constants
#define BB 4
#define SS 256
#define DD 256
#define VV 128
#define EE 64
#define CC 192
#define LN_EPS 1e-3f

// main-kernel smem byte offsets
// W: [192 n][72 k] fp16 (27648 B); two db buffers [256][33] f32 (33792 B each);
// X staging [256][72] fp16 (36864 B, transient) overlaid across db0(+head of db1).
#define WH_OFF  0
#define DB0_OFF 27648
#define DB1_OFF 61440
#define XH_OFF  DB0_OFF
#define AUX     95232
#define OFF_QS   (AUX)
#define OFF_WDS  (AUX + 256)
#define OFF_S1K  (AUX + 512)
#define OFF_S2K  (AUX + 768)
#define OFF_S1V  (AUX + 1024)
#define OFF_S2V  (AUX + 1280)
#define OFF_BES  (AUX + 1536)
#define OFF_SSUM (AUX + 1792)
#define OFF_SSQ  (AUX + 2816)
#define OFF_RED  (AUX + 3840)
#define SMEM_MAIN (AUX + 4864)   // 100096 bytes -> 2 CTAs/SM

// ---------------- device scratch ----------------
__device__ __align__(16) float g_Wall[128 * 192];    // rows 0..127 (for g1)
__device__ float g_S1k[64], g_S2k[64], g_S1v[64], g_S2v[64];
__device__ float g_q[BB * DD * 64];
__device__ float g_wd[BB * DD * 64];
__device__ float g_o[BB * DD * 64];
__device__ __align__(16) float g_G1T[192 * BB * SS];  // TRANSPOSED: [n][b*s]
__device__ float g_sv[BB * SS], g_sq[BB * SS];
__device__ __align__(16) __half g_WTh[192 * 72];      // W2^T fp16, [n][k] padded

// ---------------- mma.sync helper (fp16 in, fp32 accum; baseline sm_80+ PTX) ----------------
__device__ __forceinline__ void mma16816(float* c, const uint32_t* a, const uint32_t* b) {
    asm volatile(
        "mma.sync.aligned.m16n8k16.row.col.f32.f16.f16.f32 "
        "{%0,%1,%2,%3}, {%4,%5,%6,%7}, {%8,%9}, {%0,%1,%2,%3};"
        : "+f"(c[0]), "+f"(c[1]), "+f"(c[2]), "+f"(c[3])
        : "r"(a[0]), "r"(a[1]), "r"(a[2]), "r"(a[3]), "r"(b[0]), "r"(b[1]));
}

// GEMM of one 32-col phase into db with conflict-free swizzled stores.
__device__ __forceinline__ void gemm_phase(
    const unsigned char* smm, float* db, int p, int g, int tc, int wid,
    const uint32_t (&ahf)[2][4][4]) {
    #pragma unroll
    for (int nt = 0; nt < 4; nt++) {
        int n = p * 32 + nt * 8 + g;
        uint32_t bhf[4][2];
        #pragma unroll
        for (int ks = 0; ks < 4; ks++) {
            int kk = tc * 2 + 16 * ks;
            bhf[ks][0] = *(const uint32_t*)(smm + WH_OFF + (n * 72 + kk) * 2);
            bhf[ks][1] = *(const uint32_t*)(smm + WH_OFF + (n * 72 + kk + 8) * 2);
        }
        float a0[2][4];
        #pragma unroll
        for (int mt = 0; mt < 2; mt++)
            #pragma unroll
            for (int i = 0; i < 4; i++) a0[mt][i] = 0.f;
        #pragma unroll
        for (int ks = 0; ks < 4; ks++) {
            #pragma unroll
            for (int mt = 0; mt < 2; mt++)
                mma16816(a0[mt], ahf[mt][ks], bhf[ks]);
        }
        #pragma unroll
        for (int mt = 0; mt < 2; mt++) {
            int r0 = wid * 32 + mt * 16 + g;
            int r1 = r0 + 8;
            int col = nt * 8 + tc * 2;
            // swizzled slot: (col + 4*row) & 31 -> store banks (5*row+col) mod 32, distinct
            db[r0 * 33 + ((col + 4 * r0) & 31)]     = a0[mt][0];
            db[r0 * 33 + ((col + 1 + 4 * r0) & 31)] = a0[mt][1];
            db[r1 * 33 + ((col + 4 * r1) & 31)]     = a0[mt][2];
            db[r1 * 33 + ((col + 1 + 4 * r1) & 31)] = a0[mt][3];
        }
    }
}

// ---------------- prep: all weight preprocessing in one kernel ----------------
__global__ void prep_all(const float* __restrict__ g_in, const float* __restrict__ b_in,
                         const float* __restrict__ Wk, const float* __restrict__ bk,
                         const float* __restrict__ Wv, const float* __restrict__ bv,
                         const float* __restrict__ We) {
    int bid = blockIdx.x;
    int tid = threadIdx.x;   // 192
    if (bid < 128) {
        int c = bid, j = tid;
        float g = g_in[c];
        float val;
        if (j < 64)        val = g * Wk[c * 64 + j];
        else if (j < 128)  val = g * Wv[c * 64 + (j - 64)];
        else               val = We[c * 64 + (j - 128)];       // c < 128
        g_Wall[c * 192 + j] = val;
    } else if (bid < 320) {
        int n = bid - 128;
        if (tid < 64) {
            int k = tid;
            int c = 128 + k;
            float g = g_in[c];
            float w;
            if (n < 64)        w = g * Wk[c * 64 + n];
            else if (n < 128)  w = g * Wv[c * 64 + (n - 64)];
            else               w = We[(c + 128) * 64 + (n - 128)];
            g_WTh[n * 72 + k] = __float2half_rn(w);
            if (k >= 56) g_WTh[n * 72 + 8 + k] = __float2half_rn(0.f);
        }
    } else {
        if (tid < 64) {
            int j = tid;
            float s1 = 0.f, s2 = 0.f;
            for (int c = 0; c < CC; c++) {
                float w = Wk[c * 64 + j];
                s1 += g_in[c] * w;
                s2 += b_in[c] * w;
            }
            g_S1k[j] = s1;
            g_S2k[j] = s2 + bk[j];
        } else if (tid < 128) {
            int j = tid - 64;
            float s1 = 0.f, s2 = 0.f;
            for (int c = 0; c < CC; c++) {
                float w = Wv[c * 64 + j];
                s1 += g_in[c] * w;
                s2 += b_in[c] * w;
            }
            g_S1v[j] = s1;
            g_S2v[j] = s2 + bv[j];
        }
    }
}

// ---------------- G1T[n][bs] = (Vsrc @ Wall[0:128,:])^T  (+ row sums for LN) ----------------
__global__ void __launch_bounds__(256) g1_kernel(const float* __restrict__ Vsrc) {
    extern __shared__ float smf[];
    float* xt = smf;           // [128 c][8 r]
    float* ws = smf + 1024;    // [64 c][192 n]
    int bs0 = blockIdx.x * 8;
    int tid = threadIdx.x;
    int tx = tid & 31, ty = tid >> 5;

    for (int idx = tid; idx < 1024; idx += 256) {
        int c = idx & 127, r = idx >> 7;
        xt[c * 8 + r] = Vsrc[(bs0 + r) * VV + c];
    }
    __syncthreads();
    if (tid < 8) {
        float s = 0.f, ss = 0.f;
        for (int c = 0; c < VV; c++) {
            float x = xt[c * 8 + tid];
            s += x; ss += x * x;
        }
        g_sv[bs0 + tid] = s;
        g_sq[bs0 + tid] = ss;
    }

    float acc[6];
    #pragma unroll
    for (int i = 0; i < 6; i++) acc[i] = 0.f;

    for (int h = 0; h < 2; h++) {
        __syncthreads();
        const float4* src = (const float4*)(g_Wall + h * 64 * 192);
        float4* dst = (float4*)ws;
        for (int idx = tid; idx < 3072; idx += 256) dst[idx] = src[idx];
        __syncthreads();
        #pragma unroll 4
        for (int c = 0; c < 64; c++) {
            float x = xt[(h * 64 + c) * 8 + ty];
            const float* wr = ws + c * 192 + tx;
            #pragma unroll
            for (int i = 0; i < 6; i++) acc[i] = fmaf(x, wr[i * 32], acc[i]);
        }
    }
    #pragma unroll
    for (int i = 0; i < 6; i++)
        g_G1T[(size_t)(tx + 32 * i) * (BB * SS) + bs0 + ty] = acc[i];
}

// ---------------- per-(b,d): LN(V_dst) -> q, and wd GEMV (4 bd per block) ----------------
__global__ void __launch_bounds__(512) qwd_kernel(
    const float* __restrict__ Vdst, const float* __restrict__ g_vd,
    const float* __restrict__ b_vd, const float* __restrict__ Wq,
    const float* __restrict__ bq, const float* __restrict__ We) {
    __shared__ float vrow[4][VV];
    __shared__ float vn[4][VV];
    __shared__ float rsum[4][4], rsq[4][4];
    __shared__ float smu[4], srstd[4];

    int grp = threadIdx.x >> 7;
    int tid = threadIdx.x & 127;
    int bd = blockIdx.x * 4 + grp;

    float x = Vdst[bd * VV + tid];
    vrow[grp][tid] = x;

    float s = x, ss = x * x;
    for (int o = 16; o; o >>= 1) {
        s  += __shfl_down_sync(0xffffffffu, s, o);
        ss += __shfl_down_sync(0xffffffffu, ss, o);
    }
    if ((tid & 31) == 0) { rsum[grp][tid >> 5] = s; rsq[grp][tid >> 5] = ss; }
    __syncthreads();
    if (tid == 0) {
        float S = rsum[grp][0] + rsum[grp][1] + rsum[grp][2] + rsum[grp][3];
        float Q = rsq[grp][0] + rsq[grp][1] + rsq[grp][2] + rsq[grp][3];
        float m = S * (1.f / VV);
        float var = Q * (1.f / VV) - m * m;
        smu[grp] = m;
        srstd[grp] = rsqrtf(var + LN_EPS);
    }
    __syncthreads();
    vn[grp][tid] = (x - smu[grp]) * srstd[grp] * g_vd[tid] + b_vd[tid];
    __syncthreads();

    if (tid < 64) {
        float q = bq[tid];
        #pragma unroll 4
        for (int j = 0; j < VV; j++) q += vn[grp][j] * __ldg(Wq + j * 64 + tid);
        g_q[bd * 64 + tid] = fmaxf(q, 0.f);
    } else {
        int t = tid - 64;
        float w = 0.f;
        #pragma unroll 4
        for (int j = 0; j < VV; j++) w += vrow[grp][j] * __ldg(We + (128 + j) * 64 + t);
        g_wd[bd * 64 + t] = w;
    }
}

// ---------------- main fused kernel: 2 (b,d) pairs per block, pipelined phases ----------------
__global__ void __launch_bounds__(256, 2) main_kernel(
    const float* __restrict__ Egl, const float* __restrict__ A,
    const float* __restrict__ be, float* __restrict__ outE) {
    extern __shared__ __align__(16) unsigned char smm[];
    int tid = threadIdx.x;
    int lane = tid & 31, wid = tid >> 5;
    int bx = blockIdx.x;
    int d0 = (bx & 127) * 2, b = bx >> 7;

    float* s1k  = (float*)(smm + OFF_S1K);
    float* s2k  = (float*)(smm + OFF_S2K);
    float* s1v  = (float*)(smm + OFF_S1V);
    float* s2v  = (float*)(smm + OFF_S2V);
    float* bes  = (float*)(smm + OFF_BES);
    float* qs   = (float*)(smm + OFF_QS);
    float* wds  = (float*)(smm + OFF_WDS);
    float* ssum = (float*)(smm + OFF_SSUM);
    float* ssq  = (float*)(smm + OFF_SSQ);
    float* red  = (float*)(smm + OFF_RED);
    float* db0  = (float*)(smm + DB0_OFF);
    float* db1  = (float*)(smm + DB1_OFF);
    if (tid < 64) {
        s1k[tid] = g_S1k[tid]; s2k[tid] = g_S2k[tid];
        s1v[tid] = g_S1v[tid]; s2v[tid] = g_S2v[tid];
        bes[tid] = be[tid];
    }

    // stage W2^T fp16 into smem ONCE for both d values
    {
        const uint4* sh = (const uint4*)g_WTh;
        uint4* dh = (uint4*)(smm + WH_OFF);
        #pragma unroll 4
        for (int i = tid; i < 1728; i += 256) dh[i] = sh[i];
    }

    int g = lane >> 2, tc = lane & 3;
    int r = tid;                       // per-thread row
    size_t bs = (size_t)(b * SS + r);
    int gbs = b * SS + r;

    #pragma unroll 1
    for (int it2 = 0; it2 < 2; it2++) {
        int d = d0 + it2;
        int bd = b * DD + d;
        if (tid < 64) {
            qs[tid]  = g_q[bd * 64 + tid];
            wds[tid] = g_wd[bd * 64 + tid];
        }
        __syncthreads();   // db buffers free from previous iter; qs/wds ready ordering

        // ---- single-pass X staging (fp16 hi), coalesced ----
        #pragma unroll
        for (int itr = 0; itr < 16; itr++) {
            int idx = itr * 256 + tid;        // 0..4095
            int row = idx >> 4;               // 0..255
            int seg = idx & 15;               // 0..15
            float4 u = __ldg((const float4*)(Egl + ((size_t)(b * SS + row) * DD + d) * EE) + seg);
            float ps = u.x + u.y + u.z + u.w;
            float pq = u.x * u.x + u.y * u.y + u.z * u.z + u.w * u.w;
            #pragma unroll
            for (int o = 8; o; o >>= 1) {
                ps += __shfl_xor_sync(0xffffffffu, ps, o);
                pq += __shfl_xor_sync(0xffffffffu, pq, o);
            }
            if ((lane & 15) == 0) { ssum[row] = ps; ssq[row] = pq; }
            __half2 ph0 = __halves2half2(__float2half_rn(u.x), __float2half_rn(u.y));
            __half2 ph1 = __halves2half2(__float2half_rn(u.z), __float2half_rn(u.w));
            uint32_t boff = (uint32_t)(row * 72 + seg * 4) * 2;
            *(uint2*)(smm + XH_OFF + boff) = make_uint2(*(uint32_t*)&ph0, *(uint32_t*)&ph1);
        }
        __syncthreads();

        // ---- fragment pickup (all warps, full 256 rows) ----
        uint32_t ahf[2][4][4];
        #pragma unroll
        for (int mt = 0; mt < 2; mt++) {
            int r0 = wid * 32 + mt * 16 + g;
            #pragma unroll
            for (int ks = 0; ks < 4; ks++) {
                int c0 = tc * 2 + 16 * ks;
                ahf[mt][ks][0] = *(const uint32_t*)(smm + XH_OFF + (r0 * 72 + c0) * 2);
                ahf[mt][ks][1] = *(const uint32_t*)(smm + XH_OFF + ((r0 + 8) * 72 + c0) * 2);
                ahf[mt][ks][2] = *(const uint32_t*)(smm + XH_OFF + (r0 * 72 + c0 + 8) * 2);
                ahf[mt][ks][3] = *(const uint32_t*)(smm + XH_OFF + ((r0 + 8) * 72 + c0 + 8) * 2);
            }
        }
        // LN stats (ssum/ssq valid; X region about to be overwritten by db)
        float av = __ldg(A + bs * DD + d);
        float mu = (av * g_sv[bs] + ssum[r]) * (1.f / CC);
        float msq = (av * av * g_sq[bs] + ssq[r]) * (1.f / CC);
        float rstd = rsqrtf(msq - mu * mu + LN_EPS);
        __syncthreads();

        float sc[8];
        #pragma unroll
        for (int h = 0; h < 8; h++) sc[h] = 0.f;

        gemm_phase(smm, db0, 0, g, tc, wid, ahf);
        __syncthreads();

        #pragma unroll 1
        for (int p = 0; p < 6; p++) {
            if (p < 5) gemm_phase(smm, (p & 1) ? db0 : db1, p + 1, g, tc, wid, ahf);
            float* db = (p & 1) ? db1 : db0;

            if (p < 2) {
                #pragma unroll
                for (int j = 0; j < 32; j++) {
                    int jg = p * 32 + j;
                    float gv = __ldg(g_G1T + (size_t)jg * (BB * SS) + gbs);
                    float yf = av * gv + db[r * 33 + ((j + 4 * r) & 31)];
                    float kk = fmaxf(rstd * (yf - mu * s1k[jg]) + s2k[jg], 0.f);
                    sc[jg >> 3] += qs[jg] * kk;
                }
                if (p == 1) {
                    float mx = sc[0] * 0.35355339059327373f;
                    #pragma unroll
                    for (int h = 0; h < 8; h++) { sc[h] *= 0.35355339059327373f; mx = fmaxf(mx, sc[h]); }
                    float sum = 0.f;
                    #pragma unroll
                    for (int h = 0; h < 8; h++) { sc[h] = __expf(sc[h] - mx); sum += sc[h]; }
                    float inv = 1.f / sum;
                    #pragma unroll
                    for (int h = 0; h < 8; h++) sc[h] *= inv;
                }
                __syncthreads();
            } else if (p < 4) {
                int q = p - 2;
                #pragma unroll
                for (int j = 0; j < 32; j++) {
                    int jg = q * 32 + j;
                    int slot = r * 33 + ((j + 4 * r) & 31);
                    float gv = __ldg(g_G1T + (size_t)(64 + jg) * (BB * SS) + gbs);
                    float yf = av * gv + db[slot];
                    float vv = fmaxf(rstd * (yf - mu * s1v[jg]) + s2v[jg], 0.f);
                    db[slot] = sc[jg >> 3] * vv;   // in-place, same swizzled slot
                }
                __syncthreads();
                {
                    int col = tid & 31, qq = tid >> 5;
                    float s = 0.f;
                    int rr0 = qq * 32;
                    #pragma unroll 8
                    for (int rr = rr0; rr < rr0 + 32; rr++)
                        s += db[rr * 33 + ((col + 4 * rr) & 31)];
                    red[qq * 32 + col] = s;
                }
                __syncthreads();
                if (tid < 32) {
                    float s = ((red[tid] + red[32 + tid]) + (red[64 + tid] + red[96 + tid]))
                            + ((red[128 + tid] + red[160 + tid]) + (red[192 + tid] + red[224 + tid]));
                    g_o[(size_t)bd * 64 + q * 32 + tid] = s;
                }
                __syncthreads();
            } else {
                int q = p - 4;
                #pragma unroll
                for (int j = 0; j < 32; j++) {
                    int jg = q * 32 + j;
                    int slot = r * 33 + ((j + 4 * r) & 31);
                    float gv = __ldg(g_G1T + (size_t)(128 + jg) * (BB * SS) + gbs);
                    float y = av * gv + db[slot] + av * wds[jg] + bes[jg];
                    db[slot] = fmaxf(y, 0.f);
                }
                __syncthreads();
                #pragma unroll 4
                for (int rr = 0; rr < 32; rr++) {
                    int row = wid * 32 + rr;
                    outE[((size_t)(b * SS + row) * DD + d) * EE + q * 32 + lane] =
                        db[row * 33 + ((lane + 4 * row) & 31)];
                }
                if (p == 4) __syncthreads();
            }
        }
    }
}

// ---------------- finalize: V_dst_out = V_dst + relu(o @ Wo + bo); also outA = 1 ----------------
__global__ void __launch_bounds__(128) fin_kernel(
    const float* __restrict__ Vdst, const float* __restrict__ Wo,
    const float* __restrict__ bo, float* __restrict__ outV,
    float* __restrict__ outA) {
    __shared__ float os[64];
    int bd = blockIdx.x;
    int tid = threadIdx.x;
    if (tid < 64) os[tid] = g_o[(size_t)bd * 64 + tid];
    outA[bd * 256 + tid] = 1.0f;
    outA[bd * 256 + 128 + tid] = 1.0f;
    __syncthreads();
    float a = bo[tid];
    #pragma unroll 4
    for (int t = 0; t < 64; t++) a += os[t] * __ldg(Wo + t * VV + tid);
    outV[bd * VV + tid] = Vdst[bd * VV + tid] + fmaxf(a, 0.f);
}

// ---------------- launch ----------------
extern "C" void kernel_launch(void* const* d_in, const int* in_sizes, int n_in,
                              void* d_out, int out_size) {
    const float* V_src = (const float*)d_in[0];
    const float* V_dst = (const float*)d_in[1];
    const float* E     = (const float*)d_in[2];
    const float* A     = (const float*)d_in[3];
    const float* g_vd  = (const float*)d_in[4];
    const float* b_vd  = (const float*)d_in[5];
    const float* g_in  = (const float*)d_in[6];
    const float* b_in  = (const float*)d_in[7];
    const float* Wq    = (const float*)d_in[8];
    const float* bq    = (const float*)d_in[9];
    const float* Wk    = (const float*)d_in[10];
    const float* bk    = (const float*)d_in[11];
    const float* Wv    = (const float*)d_in[12];
    const float* bv    = (const float*)d_in[13];
    const float* Wo    = (const float*)d_in[14];
    const float* bo    = (const float*)d_in[15];
    const float* We    = (const float*)d_in[16];
    const float* be    = (const float*)d_in[17];
    // d_in[18] = Wa, d_in[19] = ba: unused — softmax over singleton axis is exactly 1.

    float* outV = (float*)d_out;                       // [4,256,128]
    float* outE = outV + BB * DD * VV;                 // [4,256,256,64]
    float* outA = outE + (size_t)BB * SS * DD * EE;    // [4,256,256]

    const int SMEM_G1 = (1024 + 64 * 192) * (int)sizeof(float);
    cudaFuncSetAttribute(main_kernel, cudaFuncAttributeMaxDynamicSharedMemorySize, SMEM_MAIN);
    cudaFuncSetAttribute(g1_kernel, cudaFuncAttributeMaxDynamicSharedMemorySize, SMEM_G1);

    prep_all<<<321, 192>>>(g_in, b_in, Wk, bk, Wv, bv, We);
    g1_kernel<<<BB * SS / 8, 256, SMEM_G1>>>(V_src);
    qwd_kernel<<<BB * DD / 4, 512>>>(V_dst, g_vd, b_vd, Wq, bq, We);
    main_kernel<<<BB * DD / 2, 256, SMEM_MAIN>>>(E, A, be, outE);
    fin_kernel<<<BB * DD, 128>>>(V_dst, Wo, bo, outV, outA);
}

// round 16
// speedup vs baseline: 1.1022x; 1.1022x over previous
#include <cuda_runtime.h>
#include <cuda_fp16.h>
#include <math.h>
#include <stdint.h>

// Problem constants
#define BB 4
#define SS 256
#define DD 256
#define VV 128
#define EE 64
#define CC 192
#define LN_EPS 1e-3f

// main-kernel smem byte offsets (R13 layout)
#define WH_OFF  0
#define DB0_OFF 27648
#define DB1_OFF 61440
#define XH_OFF  DB0_OFF
#define AUX     95232
#define OFF_QS   (AUX)
#define OFF_WDS  (AUX + 256)
#define OFF_S1K  (AUX + 512)
#define OFF_S2K  (AUX + 768)
#define OFF_S1V  (AUX + 1024)
#define OFF_S2V  (AUX + 1280)
#define OFF_BES  (AUX + 1536)
#define OFF_SSUM (AUX + 1792)
#define OFF_SSQ  (AUX + 2816)
#define OFF_RED  (AUX + 3840)
#define SMEM_MAIN (AUX + 4864)   // 100096 bytes -> 2 CTAs/SM

// mega_pre grid layout
#define G1_BLOCKS  128
#define QWD_BLOCKS 512          // 2 bd per block -> 1024 bd total (FIX: was 256)
#define WT_BLOCKS  48

// ---------------- device scratch ----------------
__device__ float g_S1k[64], g_S2k[64], g_S1v[64], g_S2v[64];
__device__ float g_q[BB * DD * 64];
__device__ float g_wd[BB * DD * 64];
__device__ float g_o[BB * DD * 64];
__device__ __align__(16) float g_G1T[192 * BB * SS];  // TRANSPOSED: [n][b*s]
__device__ float g_sv[BB * SS], g_sq[BB * SS];
__device__ __align__(16) __half g_WTh[192 * 72];      // W2^T fp16, [n][k] padded

// ---------------- mma.sync helper (fp16 in, fp32 accum; baseline sm_80+ PTX) ----------------
__device__ __forceinline__ void mma16816(float* c, const uint32_t* a, const uint32_t* b) {
    asm volatile(
        "mma.sync.aligned.m16n8k16.row.col.f32.f16.f16.f32 "
        "{%0,%1,%2,%3}, {%4,%5,%6,%7}, {%8,%9}, {%0,%1,%2,%3};"
        : "+f"(c[0]), "+f"(c[1]), "+f"(c[2]), "+f"(c[3])
        : "r"(a[0]), "r"(a[1]), "r"(a[2]), "r"(a[3]), "r"(b[0]), "r"(b[1]));
}

// GEMM of one 32-col phase into db (no barriers inside); pure fp16 path
__device__ __forceinline__ void gemm_phase(
    const unsigned char* smm, float* db, int p, int g, int tc, int wid,
    const uint32_t (&ahf)[2][4][4]) {
    #pragma unroll
    for (int nt = 0; nt < 4; nt++) {
        int n = p * 32 + nt * 8 + g;
        uint32_t bhf[4][2];
        #pragma unroll
        for (int ks = 0; ks < 4; ks++) {
            int kk = tc * 2 + 16 * ks;
            bhf[ks][0] = *(const uint32_t*)(smm + WH_OFF + (n * 72 + kk) * 2);
            bhf[ks][1] = *(const uint32_t*)(smm + WH_OFF + (n * 72 + kk + 8) * 2);
        }
        float a0[2][4];
        #pragma unroll
        for (int mt = 0; mt < 2; mt++)
            #pragma unroll
            for (int i = 0; i < 4; i++) a0[mt][i] = 0.f;
        #pragma unroll
        for (int ks = 0; ks < 4; ks++) {
            #pragma unroll
            for (int mt = 0; mt < 2; mt++)
                mma16816(a0[mt], ahf[mt][ks], bhf[ks]);
        }
        #pragma unroll
        for (int mt = 0; mt < 2; mt++) {
            int r0 = wid * 32 + mt * 16 + g;
            int col = nt * 8 + tc * 2;
            db[r0 * 33 + col]           = a0[mt][0];
            db[r0 * 33 + col + 1]       = a0[mt][1];
            db[(r0 + 8) * 33 + col]     = a0[mt][2];
            db[(r0 + 8) * 33 + col + 1] = a0[mt][3];
        }
    }
}

// ---------------- mega_pre: g1 + qwd + WTh prep + sums in one heterogeneous grid ----------------
// blocks [0,128)            : G1T tiles (8 s-rows each), weight tile built on the fly
// blocks [128,640)          : qwd for 2 bd each (1024 bd total)
// blocks [640,688)          : W2^T fp16 image, 4 n-rows each
// block  688                : S1/S2 sums
__global__ void __launch_bounds__(256) mega_pre(
    const float* __restrict__ Vsrc, const float* __restrict__ Vdst,
    const float* __restrict__ g_in, const float* __restrict__ b_in,
    const float* __restrict__ g_vd, const float* __restrict__ b_vd,
    const float* __restrict__ Wq, const float* __restrict__ bq,
    const float* __restrict__ Wk, const float* __restrict__ bk,
    const float* __restrict__ Wv, const float* __restrict__ bv,
    const float* __restrict__ We) {
    __shared__ float smp[13312];   // g1: xt[1024] + ws[12288]; qwd carves a slice
    int bid = blockIdx.x;
    int tid = threadIdx.x;

    if (bid < G1_BLOCKS) {
        // ---------- G1T ----------
        float* xt = smp;            // [128 c][8 r]
        float* ws = smp + 1024;     // [64 c][192 n]
        int bs0 = bid * 8;
        int tx = tid & 31, ty = tid >> 5;

        for (int idx = tid; idx < 1024; idx += 256) {
            int c = idx & 127, r = idx >> 7;
            xt[c * 8 + r] = Vsrc[(bs0 + r) * VV + c];
        }
        __syncthreads();
        if (tid < 8) {
            float s = 0.f, ss = 0.f;
            for (int c = 0; c < VV; c++) {
                float x = xt[c * 8 + tid];
                s += x; ss += x * x;
            }
            g_sv[bs0 + tid] = s;
            g_sq[bs0 + tid] = ss;
        }

        float acc[6];
        #pragma unroll
        for (int i = 0; i < 6; i++) acc[i] = 0.f;

        for (int h = 0; h < 2; h++) {
            __syncthreads();
            // build ws[c][192] on the fly: [g*Wk | g*Wv | We] rows h*64..h*64+63
            for (int idx = tid; idx < 3072; idx += 256) {
                int c = h * 64 + idx / 48;
                int jq = idx % 48;
                float4 wv;
                if (jq < 16) {
                    wv = __ldg((const float4*)Wk + c * 16 + jq);
                    float gg = __ldg(g_in + c);
                    wv.x *= gg; wv.y *= gg; wv.z *= gg; wv.w *= gg;
                } else if (jq < 32) {
                    wv = __ldg((const float4*)Wv + c * 16 + (jq - 16));
                    float gg = __ldg(g_in + c);
                    wv.x *= gg; wv.y *= gg; wv.z *= gg; wv.w *= gg;
                } else {
                    wv = __ldg((const float4*)We + c * 16 + (jq - 32));
                }
                ((float4*)ws)[idx] = wv;
            }
            __syncthreads();
            #pragma unroll 4
            for (int c = 0; c < 64; c++) {
                float x = xt[(h * 64 + c) * 8 + ty];
                const float* wr = ws + c * 192 + tx;
                #pragma unroll
                for (int i = 0; i < 6; i++) acc[i] = fmaf(x, wr[i * 32], acc[i]);
            }
        }
        #pragma unroll
        for (int i = 0; i < 6; i++)
            g_G1T[(size_t)(tx + 32 * i) * (BB * SS) + bs0 + ty] = acc[i];

    } else if (bid < G1_BLOCKS + QWD_BLOCKS) {
        // ---------- qwd: 2 bd per block ----------
        float* vrow = smp;              // [2][128]
        float* vn   = smp + 256;        // [2][128]
        float* rsum = smp + 512;        // [2][4]
        float* rsq  = smp + 520;        // [2][4]
        float* smu  = smp + 528;        // [2]
        float* srst = smp + 530;        // [2]

        int grp = tid >> 7;             // 0..1
        int t = tid & 127;
        int bd = (bid - G1_BLOCKS) * 2 + grp;

        float x = Vdst[bd * VV + t];
        vrow[grp * 128 + t] = x;

        float s = x, ss = x * x;
        for (int o = 16; o; o >>= 1) {
            s  += __shfl_down_sync(0xffffffffu, s, o);
            ss += __shfl_down_sync(0xffffffffu, ss, o);
        }
        if ((t & 31) == 0) { rsum[grp * 4 + (t >> 5)] = s; rsq[grp * 4 + (t >> 5)] = ss; }
        __syncthreads();
        if (t == 0) {
            float S = rsum[grp * 4] + rsum[grp * 4 + 1] + rsum[grp * 4 + 2] + rsum[grp * 4 + 3];
            float Q = rsq[grp * 4] + rsq[grp * 4 + 1] + rsq[grp * 4 + 2] + rsq[grp * 4 + 3];
            float m = S * (1.f / VV);
            float var = Q * (1.f / VV) - m * m;
            smu[grp] = m;
            srst[grp] = rsqrtf(var + LN_EPS);
        }
        __syncthreads();
        vn[grp * 128 + t] = (x - smu[grp]) * srst[grp] * g_vd[t] + b_vd[t];
        __syncthreads();

        if (t < 64) {
            float q = bq[t];
            #pragma unroll 4
            for (int j = 0; j < VV; j++) q += vn[grp * 128 + j] * __ldg(Wq + j * 64 + t);
            g_q[bd * 64 + t] = fmaxf(q, 0.f);
        } else {
            int tt = t - 64;
            float w = 0.f;
            #pragma unroll 4
            for (int j = 0; j < VV; j++) w += vrow[grp * 128 + j] * __ldg(We + (128 + j) * 64 + tt);
            g_wd[bd * 64 + tt] = w;
        }

    } else if (bid < G1_BLOCKS + QWD_BLOCKS + WT_BLOCKS) {
        // ---------- W2^T fp16 image: 4 n per block ----------
        int n = (bid - G1_BLOCKS - QWD_BLOCKS) * 4 + (tid >> 6);
        int k = tid & 63;
        int c = 128 + k;
        float g = __ldg(g_in + c);
        float w;
        if (n < 64)        w = g * __ldg(Wk + c * 64 + n);
        else if (n < 128)  w = g * __ldg(Wv + c * 64 + (n - 64));
        else               w = __ldg(We + (c + 128) * 64 + (n - 128));
        g_WTh[n * 72 + k] = __float2half_rn(w);
        if (k >= 56) g_WTh[n * 72 + 8 + k] = __float2half_rn(0.f);

    } else {
        // ---------- S1/S2 sums ----------
        if (tid < 64) {
            int j = tid;
            float s1 = 0.f, s2 = 0.f;
            for (int c = 0; c < CC; c++) {
                float w = __ldg(Wk + c * 64 + j);
                s1 += __ldg(g_in + c) * w;
                s2 += __ldg(b_in + c) * w;
            }
            g_S1k[j] = s1;
            g_S2k[j] = s2 + bk[j];
        } else if (tid < 128) {
            int j = tid - 64;
            float s1 = 0.f, s2 = 0.f;
            for (int c = 0; c < CC; c++) {
                float w = __ldg(Wv + c * 64 + j);
                s1 += __ldg(g_in + c) * w;
                s2 += __ldg(b_in + c) * w;
            }
            g_S1v[j] = s1;
            g_S2v[j] = s2 + bv[j];
        }
    }
}

// ---------------- main fused kernel (R13 config): one (b,d)/block, double-buffered pipeline ----------------
__global__ void __launch_bounds__(256, 2) main_kernel(
    const float* __restrict__ Egl, const float* __restrict__ A,
    const float* __restrict__ be, float* __restrict__ outE) {
    extern __shared__ __align__(16) unsigned char smm[];
    int tid = threadIdx.x;
    int lane = tid & 31, wid = tid >> 5;
    int bx = blockIdx.x;
    int d = bx & 255, b = bx >> 8;
    int bd = b * DD + d;

    float* qs   = (float*)(smm + OFF_QS);
    float* wds  = (float*)(smm + OFF_WDS);
    float* s1k  = (float*)(smm + OFF_S1K);
    float* s2k  = (float*)(smm + OFF_S2K);
    float* s1v  = (float*)(smm + OFF_S1V);
    float* s2v  = (float*)(smm + OFF_S2V);
    float* bes  = (float*)(smm + OFF_BES);
    float* ssum = (float*)(smm + OFF_SSUM);
    float* ssq  = (float*)(smm + OFF_SSQ);
    float* red  = (float*)(smm + OFF_RED);
    float* db0  = (float*)(smm + DB0_OFF);
    float* db1  = (float*)(smm + DB1_OFF);
    if (tid < 64) {
        qs[tid]  = g_q[bd * 64 + tid];
        wds[tid] = g_wd[bd * 64 + tid];
        s1k[tid] = g_S1k[tid]; s2k[tid] = g_S2k[tid];
        s1v[tid] = g_S1v[tid]; s2v[tid] = g_S2v[tid];
        bes[tid] = be[tid];
    }

    // stage W2^T fp16 into smem (27648 B)
    {
        const uint4* sh = (const uint4*)g_WTh;
        uint4* dh = (uint4*)(smm + WH_OFF);
        #pragma unroll 4
        for (int i = tid; i < 1728; i += 256) dh[i] = sh[i];
    }

    // ---- chunked X staging (coalesced, fp16) + per-chunk fragment pickup ----
    int g = lane >> 2, tc = lane & 3;
    uint32_t ahf[2][4][4];
    int mychunk = wid >> 1;
    #pragma unroll 1
    for (int c = 0; c < 4; c++) {
        #pragma unroll
        for (int it = 0; it < 4; it++) {
            int idx = it * 256 + tid;
            int lrow = idx >> 4;
            int seg = idx & 15;
            int row = c * 64 + lrow;
            float4 u = __ldg((const float4*)(Egl + ((size_t)(b * SS + row) * DD + d) * EE) + seg);
            float ps = u.x + u.y + u.z + u.w;
            float pq = u.x * u.x + u.y * u.y + u.z * u.z + u.w * u.w;
            #pragma unroll
            for (int o = 8; o; o >>= 1) {
                ps += __shfl_xor_sync(0xffffffffu, ps, o);
                pq += __shfl_xor_sync(0xffffffffu, pq, o);
            }
            if ((lane & 15) == 0) { ssum[row] = ps; ssq[row] = pq; }
            __half2 ph0 = __halves2half2(__float2half_rn(u.x), __float2half_rn(u.y));
            __half2 ph1 = __halves2half2(__float2half_rn(u.z), __float2half_rn(u.w));
            uint32_t boff = (uint32_t)(lrow * 72 + seg * 4) * 2;
            *(uint2*)(smm + XH_OFF + boff) = make_uint2(*(uint32_t*)&ph0, *(uint32_t*)&ph1);
        }
        __syncthreads();
        if (mychunk == c) {
            int rb = (wid & 1) * 32 + g;
            #pragma unroll
            for (int mt = 0; mt < 2; mt++) {
                int r0 = rb + mt * 16;
                #pragma unroll
                for (int ks = 0; ks < 4; ks++) {
                    int c0 = tc * 2 + 16 * ks;
                    ahf[mt][ks][0] = *(const uint32_t*)(smm + XH_OFF + (r0 * 72 + c0) * 2);
                    ahf[mt][ks][1] = *(const uint32_t*)(smm + XH_OFF + ((r0 + 8) * 72 + c0) * 2);
                    ahf[mt][ks][2] = *(const uint32_t*)(smm + XH_OFF + (r0 * 72 + c0 + 8) * 2);
                    ahf[mt][ks][3] = *(const uint32_t*)(smm + XH_OFF + ((r0 + 8) * 72 + c0 + 8) * 2);
                }
            }
        }
        __syncthreads();
    }

    // per-thread row r = tid: LN stats
    int r = tid;
    size_t bs = (size_t)(b * SS + r);
    int gbs = b * SS + r;
    float av = __ldg(A + bs * DD + d);
    float mu = (av * g_sv[bs] + ssum[r]) * (1.f / CC);
    float msq = (av * av * g_sq[bs] + ssq[r]) * (1.f / CC);
    float rstd = rsqrtf(msq - mu * mu + LN_EPS);

    float sc[8];
    #pragma unroll
    for (int h = 0; h < 8; h++) sc[h] = 0.f;

    // ---- pipelined phases: GEMM(p+1) issued before epilogue(p) ----
    gemm_phase(smm, db0, 0, g, tc, wid, ahf);
    __syncthreads();

    #pragma unroll 1
    for (int p = 0; p < 6; p++) {
        if (p < 5) gemm_phase(smm, (p & 1) ? db0 : db1, p + 1, g, tc, wid, ahf);
        float* db = (p & 1) ? db1 : db0;

        if (p < 2) {
            #pragma unroll
            for (int j = 0; j < 32; j++) {
                int jg = p * 32 + j;
                float gv = __ldg(g_G1T + (size_t)jg * (BB * SS) + gbs);
                float yf = av * gv + db[r * 33 + j];
                float kk = fmaxf(rstd * (yf - mu * s1k[jg]) + s2k[jg], 0.f);
                sc[jg >> 3] += qs[jg] * kk;
            }
            if (p == 1) {
                float mx = sc[0] * 0.35355339059327373f;
                #pragma unroll
                for (int h = 0; h < 8; h++) { sc[h] *= 0.35355339059327373f; mx = fmaxf(mx, sc[h]); }
                float sum = 0.f;
                #pragma unroll
                for (int h = 0; h < 8; h++) { sc[h] = __expf(sc[h] - mx); sum += sc[h]; }
                float inv = 1.f / sum;
                #pragma unroll
                for (int h = 0; h < 8; h++) sc[h] *= inv;
            }
            __syncthreads();
        } else if (p < 4) {
            int q = p - 2;
            #pragma unroll
            for (int j = 0; j < 32; j++) {
                int jg = q * 32 + j;
                float gv = __ldg(g_G1T + (size_t)(64 + jg) * (BB * SS) + gbs);
                float yf = av * gv + db[r * 33 + j];
                float vv = fmaxf(rstd * (yf - mu * s1v[jg]) + s2v[jg], 0.f);
                db[r * 33 + j] = sc[jg >> 3] * vv;
            }
            __syncthreads();
            {
                int col = tid & 31, qq = tid >> 5;
                float s = 0.f;
                int rr0 = qq * 32;
                #pragma unroll 8
                for (int rr = rr0; rr < rr0 + 32; rr++) s += db[rr * 33 + col];
                red[qq * 32 + col] = s;
            }
            __syncthreads();
            if (tid < 32) {
                float s = ((red[tid] + red[32 + tid]) + (red[64 + tid] + red[96 + tid]))
                        + ((red[128 + tid] + red[160 + tid]) + (red[192 + tid] + red[224 + tid]));
                g_o[(size_t)bd * 64 + q * 32 + tid] = s;
            }
            __syncthreads();
        } else {
            int q = p - 4;
            #pragma unroll
            for (int j = 0; j < 32; j++) {
                int jg = q * 32 + j;
                float gv = __ldg(g_G1T + (size_t)(128 + jg) * (BB * SS) + gbs);
                float y = av * gv + db[r * 33 + j] + av * wds[jg] + bes[jg];
                db[r * 33 + j] = fmaxf(y, 0.f);
            }
            __syncthreads();
            #pragma unroll 4
            for (int rr = 0; rr < 32; rr++) {
                int row = wid * 32 + rr;
                outE[((size_t)(b * SS + row) * DD + d) * EE + q * 32 + lane] = db[row * 33 + lane];
            }
            if (p == 4) __syncthreads();
        }
    }
}

// ---------------- finalize: V_dst_out = V_dst + relu(o @ Wo + bo); also outA = 1 ----------------
__global__ void __launch_bounds__(128) fin_kernel(
    const float* __restrict__ Vdst, const float* __restrict__ Wo,
    const float* __restrict__ bo, float* __restrict__ outV,
    float* __restrict__ outA) {
    __shared__ float os[64];
    int bd = blockIdx.x;
    int tid = threadIdx.x;
    if (tid < 64) os[tid] = g_o[(size_t)bd * 64 + tid];
    outA[bd * 256 + tid] = 1.0f;
    outA[bd * 256 + 128 + tid] = 1.0f;
    __syncthreads();
    float a = bo[tid];
    #pragma unroll 4
    for (int t = 0; t < 64; t++) a += os[t] * __ldg(Wo + t * VV + tid);
    outV[bd * VV + tid] = Vdst[bd * VV + tid] + fmaxf(a, 0.f);
}

// ---------------- launch ----------------
extern "C" void kernel_launch(void* const* d_in, const int* in_sizes, int n_in,
                              void* d_out, int out_size) {
    const float* V_src = (const float*)d_in[0];
    const float* V_dst = (const float*)d_in[1];
    const float* E     = (const float*)d_in[2];
    const float* A     = (const float*)d_in[3];
    const float* g_vd  = (const float*)d_in[4];
    const float* b_vd  = (const float*)d_in[5];
    const float* g_in  = (const float*)d_in[6];
    const float* b_in  = (const float*)d_in[7];
    const float* Wq    = (const float*)d_in[8];
    const float* bq    = (const float*)d_in[9];
    const float* Wk    = (const float*)d_in[10];
    const float* bk    = (const float*)d_in[11];
    const float* Wv    = (const float*)d_in[12];
    const float* bv    = (const float*)d_in[13];
    const float* Wo    = (const float*)d_in[14];
    const float* bo    = (const float*)d_in[15];
    const float* We    = (const float*)d_in[16];
    const float* be    = (const float*)d_in[17];
    // d_in[18] = Wa, d_in[19] = ba: unused — softmax over singleton axis is exactly 1.

    float* outV = (float*)d_out;                       // [4,256,128]
    float* outE = outV + BB * DD * VV;                 // [4,256,256,64]
    float* outA = outE + (size_t)BB * SS * DD * EE;    // [4,256,256]

    cudaFuncSetAttribute(main_kernel, cudaFuncAttributeMaxDynamicSharedMemorySize, SMEM_MAIN);

    mega_pre<<<G1_BLOCKS + QWD_BLOCKS + WT_BLOCKS + 1, 256>>>(
        V_src, V_dst, g_in, b_in, g_vd, b_vd, Wq, bq, Wk, bk, Wv, bv, We);
    main_kernel<<<BB * DD, 256, SMEM_MAIN>>>(E, A, be, outE);
    fin_kernel<<<BB * DD, 128>>>(V_dst, Wo, bo, outV, outA);
}